// round 2
// baseline (speedup 1.0000x reference)
#include <cuda_runtime.h>

#define Nb 32
#define Qn 300
#define Cc 92
#define Tt 32
#define NTHR 320
#define NWARP (NTHR/32)
#define INF 1e30f

// scratch (no allocations allowed)
__device__ float g_cost [Nb * Tt * Qn];  // [batch][local target][query]   (LSA block)
__device__ float g_cost0[Nb * Tt * Qn];  // [batch][GLOBAL target 0..31][query] (for the sum)
__device__ float g_bsum[Nb];
__device__ int   g_is64;

// ---------------------------------------------------------------------------
// Detect whether tgt_labels buffer is int64 or int32 (reads 4 KB, valid both).
// ---------------------------------------------------------------------------
__global__ void detect_kernel(const int* __restrict__ lab32) {
    __shared__ int s_any;
    if (threadIdx.x == 0) s_any = 0;
    __syncthreads();
    int any = 0;
    for (int k = 1 + 2 * threadIdx.x; k < Nb * Tt; k += 2 * blockDim.x)
        if (lab32[k] != 0) any = 1;
    if (any) atomicOr(&s_any, 1);
    __syncthreads();
    if (threadIdx.x == 0) g_is64 = (s_any == 0) ? 1 : 0;
}

// ---------------------------------------------------------------------------
// Cost kernel: one thread per (batch i, query q).
//  - g_cost : vs batch i's own targets (gt = i*T + t)  -> used by the LSA
//  - g_cost0: vs GLOBAL targets t in [0,32)            -> used by the final sum
//    (this mirrors the reference's  mult[i, q_of_t, arange(T)] = 1  indexing)
// ---------------------------------------------------------------------------
__device__ __forceinline__ float pair_cost(
    float cx, float cy, float w, float h,
    float ax0, float ay0, float ax1, float ay1, float areaA,
    const float* __restrict__ l, float m, float inv_s,
    const float* __restrict__ tboxes, const int* __restrict__ lab32,
    int gt, int is64)
{
    int lab = is64 ? lab32[2 * gt] : lab32[gt];
    float pc = expf(l[lab] - m) * inv_s;

    const float* tb = tboxes + (size_t)gt * 4;
    float tx = tb[0], ty = tb[1], tw = tb[2], th = tb[3];
    float cbbox = fabsf(cx - tx) + fabsf(cy - ty) + fabsf(w - tw) + fabsf(h - th);

    float bx0 = tx - 0.5f * tw, by0 = ty - 0.5f * th;
    float bx1 = tx + 0.5f * tw, by1 = ty + 0.5f * th;
    float areaB = (bx1 - bx0) * (by1 - by0);

    float iw = fminf(ax1, bx1) - fmaxf(ax0, bx0); iw = fmaxf(iw, 0.f);
    float ih = fminf(ay1, by1) - fmaxf(ay0, by0); ih = fmaxf(ih, 0.f);
    float inter = iw * ih;
    float uni = areaA + areaB - inter;
    float iou = inter / uni;

    float cw = fmaxf(ax1, bx1) - fminf(ax0, bx0); cw = fmaxf(cw, 0.f);
    float ch = fmaxf(ay1, by1) - fminf(ay0, by0); ch = fmaxf(ch, 0.f);
    float areaC = cw * ch;
    float giou = iou - (areaC - uni) / areaC;

    return 5.f * cbbox - pc - 2.f * giou;
}

__global__ void cost_kernel(const float* __restrict__ logits,
                            const float* __restrict__ boxes,
                            const int*   __restrict__ lab32,
                            const float* __restrict__ tboxes) {
    int idx = blockIdx.x * blockDim.x + threadIdx.x;
    if (idx >= Nb * Qn) return;
    int i = idx / Qn;
    int q = idx - i * Qn;

    const float* l = logits + (size_t)idx * Cc;
    float m = -INF;
    #pragma unroll 4
    for (int c = 0; c < Cc; c++) m = fmaxf(m, l[c]);
    float s = 0.f;
    #pragma unroll 4
    for (int c = 0; c < Cc; c++) s += expf(l[c] - m);
    float inv_s = 1.f / s;

    const float* b = boxes + (size_t)idx * 4;
    float cx = b[0], cy = b[1], w = b[2], h = b[3];
    float ax0 = cx - 0.5f * w, ay0 = cy - 0.5f * h;
    float ax1 = cx + 0.5f * w, ay1 = cy + 0.5f * h;
    float areaA = (ax1 - ax0) * (ay1 - ay0);

    int is64 = g_is64;
    for (int t = 0; t < Tt; t++) {
        // diagonal block (for LSA): target gt = i*T + t
        g_cost[(size_t)(i * Tt + t) * Qn + q] =
            pair_cost(cx, cy, w, h, ax0, ay0, ax1, ay1, areaA,
                      l, m, inv_s, tboxes, lab32, i * Tt + t, is64);
        // global targets 0..31 (for the reference's sum indexing)
        g_cost0[(size_t)(i * Tt + t) * Qn + q] =
            pair_cost(cx, cy, w, h, ax0, ay0, ax1, ay1, areaA,
                      l, m, inv_s, tboxes, lab32, t, is64);
    }
}

// ---------------------------------------------------------------------------
// LSA kernel: one block per batch. Jonker-Volgenant shortest augmenting path
// on the 32x300 diagonal block (rows = targets). Final sum evaluated against
// g_cost0 (global targets 0..31) per the reference's multiplier indexing.
// ---------------------------------------------------------------------------
__global__ __launch_bounds__(NTHR, 1)
void lsa_kernel() {
    __shared__ float csh[Tt * Qn];
    __shared__ float v[Qn + 1], minv[Qn + 1], u[Tt + 1];
    __shared__ int   p[Qn + 1], way[Qn + 1];
    __shared__ unsigned char used[Qn + 1];
    __shared__ float wmin[NWARP];
    __shared__ int   wjid[NWARP];
    __shared__ int   s_j0, s_j1, s_i0;
    __shared__ float s_delta;

    const int b = blockIdx.x;
    const int tid = threadIdx.x;

    for (int k = tid; k < Tt * Qn; k += NTHR) csh[k] = g_cost[(size_t)b * Tt * Qn + k];
    for (int k = tid; k <= Qn; k += NTHR) { v[k] = 0.f; p[k] = 0; }
    if (tid <= Tt) u[tid] = 0.f;
    __syncthreads();

    for (int i = 1; i <= Tt; i++) {
        for (int k = tid; k <= Qn; k += NTHR) { minv[k] = INF; used[k] = 0; }
        if (tid == 0) { p[0] = i; s_j0 = 0; }
        __syncthreads();

        while (true) {
            if (tid == 0) { used[s_j0] = 1; s_i0 = p[s_j0]; }
            __syncthreads();
            const int i0 = s_i0;
            const int j0 = s_j0;
            const float ui0 = u[i0];

            float mv = INF;
            int   mj = Qn + 2;
            if (tid < Qn) {
                int j = tid + 1;
                if (!used[j]) {
                    float cur = csh[(i0 - 1) * Qn + (j - 1)] - ui0 - v[j];
                    if (cur < minv[j]) { minv[j] = cur; way[j] = j0; }
                    mv = minv[j];
                    mj = j;
                }
            }
            // warp argmin (tie -> smaller index)
            #pragma unroll
            for (int off = 16; off > 0; off >>= 1) {
                float ov = __shfl_down_sync(0xffffffffu, mv, off);
                int   oj = __shfl_down_sync(0xffffffffu, mj, off);
                if (ov < mv || (ov == mv && oj < mj)) { mv = ov; mj = oj; }
            }
            if ((tid & 31) == 0) { wmin[tid >> 5] = mv; wjid[tid >> 5] = mj; }
            __syncthreads();
            if (tid == 0) {
                float bv = wmin[0]; int bj = wjid[0];
                #pragma unroll
                for (int k = 1; k < NWARP; k++)
                    if (wmin[k] < bv || (wmin[k] == bv && wjid[k] < bj)) { bv = wmin[k]; bj = wjid[k]; }
                s_delta = bv; s_j1 = bj;
            }
            __syncthreads();
            const float delta = s_delta;
            const int   j1 = s_j1;

            for (int j = tid; j <= Qn; j += NTHR) {
                if (used[j]) { u[p[j]] += delta; v[j] -= delta; }
                else         { minv[j] -= delta; }
            }
            __syncthreads();
            if (tid == 0) s_j0 = j1;
            __syncthreads();
            if (p[j1] == 0) break;
        }
        // augment (serial, tiny)
        if (tid == 0) {
            int j0l = s_j0;
            while (j0l) { int j1l = way[j0l]; p[j0l] = p[j1l]; j0l = j1l; }
        }
        __syncthreads();
    }

    // sum matched costs AGAINST GLOBAL TARGETS 0..31:
    //   pair (target t = p[j]-1, query j-1)  ->  g_cost0[b][t][j-1]
    float acc = 0.f;
    for (int j = tid + 1; j <= Qn; j += NTHR)
        if (p[j]) acc += g_cost0[(size_t)(b * Tt + (p[j] - 1)) * Qn + (j - 1)];
    #pragma unroll
    for (int off = 16; off > 0; off >>= 1)
        acc += __shfl_down_sync(0xffffffffu, acc, off);
    if ((tid & 31) == 0) wmin[tid >> 5] = acc;
    __syncthreads();
    if (tid == 0) {
        float tot = 0.f;
        #pragma unroll
        for (int k = 0; k < NWARP; k++) tot += wmin[k];
        g_bsum[b] = tot;
    }
}

__global__ void final_kernel(float* out) {
    if (threadIdx.x == 0) {
        float s = 0.f;
        for (int b = 0; b < Nb; b++) s += g_bsum[b];
        out[0] = s;
    }
}

extern "C" void kernel_launch(void* const* d_in, const int* in_sizes, int n_in,
                              void* d_out, int out_size) {
    const float* pred_logits = (const float*)d_in[0];
    const float* pred_boxes  = (const float*)d_in[1];
    const int*   tgt_lab32   = (const int*)d_in[2];   // int32 view; layout auto-detected
    const float* tgt_boxes   = (const float*)d_in[3];
    float* out = (float*)d_out;

    detect_kernel<<<1, 256>>>(tgt_lab32);
    cost_kernel<<<(Nb * Qn + 255) / 256, 256>>>(pred_logits, pred_boxes, tgt_lab32, tgt_boxes);
    lsa_kernel<<<Nb, NTHR>>>();
    final_kernel<<<1, 32>>>(out);
}